// round 13
// baseline (speedup 1.0000x reference)
#include <cuda_runtime.h>
#include <cuda_bf16.h>
#include <cstdint>

static constexpr int N_ROWS = 4096;
static constexpr int N_COLS = 32000;
static constexpr int TPB    = 320;   // 8000 float4 / 320 = exactly 25 iters/thread
static constexpr int BATCH  = 5;
static constexpr int NITER  = (N_COLS / 4) / TPB / BATCH;  // 5 outer iters
static constexpr int SGRID  = 888;   // 148 SMs * 6 blocks/SM -> single wave
static constexpr int GBLK   = 32;    // gather kernel: blocks
static constexpr int GTPB   = 128;   // gather kernel: threads/block

// Scratch (no device mallocs allowed)
__device__ float g_row_sum[N_ROWS];
__device__ float g_part[GBLK];
__device__ int   g_arrive;           // zero-initialized; last block resets it

// ---------------------------------------------------------------------------
// Fast exp: Schraudolph bit-trick + cubic mantissa correction.
// Max rel error ~5.5e-4, near-zero mean. No MUFU in the hot loop.
// ---------------------------------------------------------------------------
__device__ __forceinline__ float fast_exp_term(float x) {
    float v  = fmaf(x, 12102203.0f, 1065353216.0f);
    int   iv = (int)v;
    float a  = __int_as_float(iv);
    float u  = (float)(iv & 0x007fffff);           // mantissa bits as float
    float p  = fmaf(u, fmaf(u, fmaf(u, -1.71524e-22f, 5.43943e-15f),
                            -3.35594e-8f), 1.0f);
    return a * p;
}

// ---------------------------------------------------------------------------
// Kernel 1: persistent streaming sum of exp(logits) per row.
// Grid = 888 = one full wave (6 blocks/SM at 320 threads); each block walks
// rows blockIdx.x, +888, ... eliminating the 4 wave transitions (~2360 cyc
// each) and per-wave launch/drain spread that a 4096-block grid pays.
// __ldcs: data read exactly once (evict-first).
// ---------------------------------------------------------------------------
__global__ void __launch_bounds__(TPB)
sumexp_kernel(const float* __restrict__ input)
{
    __shared__ float warp_s[TPB / 32];

    for (int row = blockIdx.x; row < N_ROWS; row += SGRID) {
        const float4* __restrict__ p =
            reinterpret_cast<const float4*>(input + (size_t)row * N_COLS);

        float s0 = 0.f, s1 = 0.f, s2 = 0.f, s3 = 0.f;

        #pragma unroll
        for (int it = 0; it < NITER; it++) {
            float4 v[BATCH];
            const int base = it * (TPB * BATCH) + threadIdx.x;
            #pragma unroll
            for (int k = 0; k < BATCH; k++)
                v[k] = __ldcs(p + base + k * TPB);
            #pragma unroll
            for (int k = 0; k < BATCH; k++) {
                s0 += fast_exp_term(v[k].x);
                s1 += fast_exp_term(v[k].y);
                s2 += fast_exp_term(v[k].z);
                s3 += fast_exp_term(v[k].w);
            }
        }
        float s = (s0 + s1) + (s2 + s3);

        #pragma unroll
        for (int o = 16; o > 0; o >>= 1)
            s += __shfl_xor_sync(0xffffffffu, s, o);

        if ((threadIdx.x & 31) == 0) warp_s[threadIdx.x >> 5] = s;
        __syncthreads();

        if (threadIdx.x == 0) {
            float S = 0.f;
            #pragma unroll
            for (int w = 0; w < TPB / 32; w++) S += warp_s[w];
            g_row_sum[row] = S;
        }
        __syncthreads();   // protect warp_s before next row's writes
    }
}

// ---------------------------------------------------------------------------
// Kernel 2 (32 blocks x 128 threads, 1 row/thread): target-dtype detection
// (redundant per block; blocks 1..31 hit L2) + target gather + focal
// epilogue + per-block partial sum + fused last-block final reduction
// (deterministic: fixed lane order; ticket counter reset for graph replay).
//
// Dtype detection: if the buffer were int32 data misread as int64, nearly
// every 8-byte slot would decode outside [0, 32000). Scanning the first
// 2048 int64 slots stays within 16 KB (the size of the int32 buffer).
// ---------------------------------------------------------------------------
__global__ void __launch_bounds__(GTPB)
gather_focal_kernel(const float* __restrict__ input, const void* __restrict__ tgt,
                    float* __restrict__ out)
{
    const int tid = threadIdx.x;
    const long long* t64 = (const long long*)tgt;

    int ok = 1;
    #pragma unroll
    for (int k = 0; k < (N_ROWS / 2) / GTPB; k++) {   // 16 slots/thread
        long long v = t64[tid + k * GTPB];
        if (v < 0 || v >= (long long)N_COLS) ok = 0;
    }
    const int is64 = __syncthreads_and(ok);

    const int row = blockIdx.x * GTPB + tid;
    long long t = is64 ? t64[row] : (long long)(((const int*)tgt)[row]);
    float S  = g_row_sum[row];
    float xt = __ldg(input + (size_t)row * N_COLS + (size_t)t);
    float logpt = xt - logf(S);
    float pt    = expf(logpt);
    float omp   = 1.0f - pt;
    // gamma: 5 iff pt < 0.2, else 3 (GAMMA_SELF == GAMMA_LT_05 == 3)
    float w3    = omp * omp * omp;
    float wgt   = (pt < 0.2f) ? w3 * omp * omp : w3;
    float acc   = -wgt * logpt;

    #pragma unroll
    for (int o = 16; o > 0; o >>= 1)
        acc += __shfl_xor_sync(0xffffffffu, acc, o);

    __shared__ float warp_s[GTPB / 32];
    __shared__ int   is_last;
    if ((tid & 31) == 0) warp_s[tid >> 5] = acc;
    __syncthreads();

    if (tid == 0) {
        float T = 0.f;
        #pragma unroll
        for (int w = 0; w < GTPB / 32; w++) T += warp_s[w];
        g_part[blockIdx.x] = T;
        __threadfence();
        is_last = (atomicAdd(&g_arrive, 1) == GBLK - 1);
    }
    __syncthreads();

    if (is_last && tid < 32) {
        __threadfence();                 // acquire all g_part writes
        float s = g_part[tid];
        #pragma unroll
        for (int o = 16; o > 0; o >>= 1)
            s += __shfl_xor_sync(0xffffffffu, s, o);
        if (tid == 0) {
            out[0]   = s;
            g_arrive = 0;                // reset for next graph replay
        }
    }
}

extern "C" void kernel_launch(void* const* d_in, const int* in_sizes, int n_in,
                              void* d_out, int out_size) {
    const float* input = (const float*)d_in[0];
    const void*  tgt   = d_in[1];
    (void)in_sizes; (void)n_in; (void)out_size;

    sumexp_kernel<<<SGRID, TPB>>>(input);
    gather_focal_kernel<<<GBLK, GTPB>>>(input, tgt, (float*)d_out);
}

// round 14
// speedup vs baseline: 1.1265x; 1.1265x over previous
#include <cuda_runtime.h>
#include <cuda_bf16.h>
#include <cstdint>

static constexpr int N_ROWS = 4096;
static constexpr int N_COLS = 32000;
static constexpr int HALF4  = (N_COLS / 4) / 2;  // 4000 float4 per half-row
static constexpr int TPB    = 160;   // 4000 / 160 = exactly 25 iters/thread
static constexpr int BATCH  = 5;
static constexpr int NITER  = HALF4 / TPB / BATCH;  // 5 outer iters
static constexpr int GBLK   = 32;    // gather kernel: blocks
static constexpr int GTPB   = 128;   // gather kernel: threads/block

// Scratch (no device mallocs allowed)
__device__ float g_half_sum[2 * N_ROWS];
__device__ float g_part[GBLK];

// ---------------------------------------------------------------------------
// Fast exp: Schraudolph bit-trick + cubic mantissa correction.
// Max rel error ~5.5e-4, near-zero mean. No MUFU in the hot loop.
// ---------------------------------------------------------------------------
__device__ __forceinline__ float fast_exp_term(float x) {
    float v  = fmaf(x, 12102203.0f, 1065353216.0f);
    int   iv = (int)v;
    float a  = __int_as_float(iv);
    float u  = (float)(iv & 0x007fffff);           // mantissa bits as float
    float p  = fmaf(u, fmaf(u, fmaf(u, -1.71524e-22f, 5.43943e-15f),
                            -3.35594e-8f), 1.0f);
    return a * p;
}

// ---------------------------------------------------------------------------
// Kernel 1: streaming sum of exp over HALF a row per block.
// 8192 blocks x 160 threads: halves the block duration vs one-row blocks,
// halving the partial-tail-wave idle loss (classic grid, HW-scheduled
// backfill — R13 showed a persistent grid quantizes and loses). Trip count
// is exactly 25 for every thread (160*5*5 = 4000 float4 = half a row).
// __ldcs: data read exactly once (evict-first).
// ---------------------------------------------------------------------------
__global__ void __launch_bounds__(TPB)
sumexp_kernel(const float* __restrict__ input)
{
    const int row  = blockIdx.x >> 1;
    const int half = blockIdx.x & 1;
    const float4* __restrict__ p =
        reinterpret_cast<const float4*>(input + (size_t)row * N_COLS) + half * HALF4;

    float s0 = 0.f, s1 = 0.f, s2 = 0.f, s3 = 0.f;

    #pragma unroll
    for (int it = 0; it < NITER; it++) {
        float4 v[BATCH];
        const int base = it * (TPB * BATCH) + threadIdx.x;
        #pragma unroll
        for (int k = 0; k < BATCH; k++)
            v[k] = __ldcs(p + base + k * TPB);
        #pragma unroll
        for (int k = 0; k < BATCH; k++) {
            s0 += fast_exp_term(v[k].x);
            s1 += fast_exp_term(v[k].y);
            s2 += fast_exp_term(v[k].z);
            s3 += fast_exp_term(v[k].w);
        }
    }
    float s = (s0 + s1) + (s2 + s3);

    #pragma unroll
    for (int o = 16; o > 0; o >>= 1)
        s += __shfl_xor_sync(0xffffffffu, s, o);

    __shared__ float warp_s[TPB / 32];
    if ((threadIdx.x & 31) == 0) warp_s[threadIdx.x >> 5] = s;
    __syncthreads();

    if (threadIdx.x == 0) {
        float S = 0.f;
        #pragma unroll
        for (int w = 0; w < TPB / 32; w++) S += warp_s[w];
        g_half_sum[blockIdx.x] = S;
    }
}

// ---------------------------------------------------------------------------
// Kernel 2 (32 blocks x 128 threads, 1 row/thread): target-dtype detection
// (redundant per block; blocks 1..31 hit L2) + target gather + focal
// epilogue + per-block partial sum. (R12 structure — known-good tail.)
//
// Dtype detection: if the buffer were int32 data misread as int64, nearly
// every 8-byte slot would decode outside [0, 32000). Scanning the first
// 2048 int64 slots stays within 16 KB (the size of the int32 buffer).
// ---------------------------------------------------------------------------
__global__ void __launch_bounds__(GTPB)
gather_focal_kernel(const float* __restrict__ input, const void* __restrict__ tgt)
{
    const int tid = threadIdx.x;
    const long long* t64 = (const long long*)tgt;

    int ok = 1;
    #pragma unroll
    for (int k = 0; k < (N_ROWS / 2) / GTPB; k++) {   // 16 slots/thread
        long long v = t64[tid + k * GTPB];
        if (v < 0 || v >= (long long)N_COLS) ok = 0;
    }
    const int is64 = __syncthreads_and(ok);

    const int row = blockIdx.x * GTPB + tid;
    long long t = is64 ? t64[row] : (long long)(((const int*)tgt)[row]);
    float S  = g_half_sum[2 * row] + g_half_sum[2 * row + 1];  // fixed order
    float xt = __ldg(input + (size_t)row * N_COLS + (size_t)t);
    float logpt = xt - logf(S);
    float pt    = expf(logpt);
    float omp   = 1.0f - pt;
    // gamma: 5 iff pt < 0.2, else 3 (GAMMA_SELF == GAMMA_LT_05 == 3)
    float w3    = omp * omp * omp;
    float wgt   = (pt < 0.2f) ? w3 * omp * omp : w3;
    float acc   = -wgt * logpt;

    #pragma unroll
    for (int o = 16; o > 0; o >>= 1)
        acc += __shfl_xor_sync(0xffffffffu, acc, o);

    __shared__ float warp_s[GTPB / 32];
    if ((tid & 31) == 0) warp_s[tid >> 5] = acc;
    __syncthreads();

    if (tid == 0) {
        float T = 0.f;
        #pragma unroll
        for (int w = 0; w < GTPB / 32; w++) T += warp_s[w];
        g_part[blockIdx.x] = T;
    }
}

// Kernel 3: one warp folds the 32 partials. Deterministic.
__global__ void __launch_bounds__(32)
final_reduce_kernel(float* __restrict__ out)
{
    float s = g_part[threadIdx.x];
    #pragma unroll
    for (int o = 16; o > 0; o >>= 1)
        s += __shfl_xor_sync(0xffffffffu, s, o);
    if (threadIdx.x == 0) out[0] = s;
}

extern "C" void kernel_launch(void* const* d_in, const int* in_sizes, int n_in,
                              void* d_out, int out_size) {
    const float* input = (const float*)d_in[0];
    const void*  tgt   = d_in[1];
    (void)in_sizes; (void)n_in; (void)out_size;

    sumexp_kernel<<<2 * N_ROWS, TPB>>>(input);
    gather_focal_kernel<<<GBLK, GTPB>>>(input, tgt);
    final_reduce_kernel<<<1, 32>>>((float*)d_out);
}

// round 15
// speedup vs baseline: 1.1306x; 1.0036x over previous
#include <cuda_runtime.h>
#include <cuda_bf16.h>
#include <cstdint>

static constexpr int N_ROWS = 4096;
static constexpr int N_COLS = 32000;
static constexpr int HALF4  = (N_COLS / 4) / 2;  // 4000 float4 per half-row
static constexpr int TPB    = 160;   // 4000 / 160 = exactly 25 iters/thread
static constexpr int BATCH  = 5;
static constexpr int NITER  = HALF4 / TPB / BATCH;  // 5 outer iters
static constexpr int GBLK   = 32;    // gather kernel: blocks
static constexpr int GTPB   = 128;   // gather kernel: threads/block

// Scratch (no device mallocs allowed)
__device__ float g_half_sum[2 * N_ROWS];
__device__ float g_part[GBLK];
__device__ int   g_arrive;           // zero-init; last block resets (graph replay)

// ---------------------------------------------------------------------------
// Fast exp: Schraudolph bit-trick + cubic mantissa correction.
// Max rel error ~5.5e-4, near-zero mean. No MUFU in the hot loop.
// ---------------------------------------------------------------------------
__device__ __forceinline__ float fast_exp_term(float x) {
    float v  = fmaf(x, 12102203.0f, 1065353216.0f);
    int   iv = (int)v;
    float a  = __int_as_float(iv);
    float u  = (float)(iv & 0x007fffff);           // mantissa bits as float
    float p  = fmaf(u, fmaf(u, fmaf(u, -1.71524e-22f, 5.43943e-15f),
                            -3.35594e-8f), 1.0f);
    return a * p;
}

// ---------------------------------------------------------------------------
// Kernel 1 (MEASURED BEST — byte-identical to R14): streaming sum of exp
// over HALF a row per block. 8192 blocks x 160 threads halves block duration
// vs one-row blocks, halving partial-tail-wave idle (classic grid,
// HW-scheduled backfill). 160*5*5 = 4000 float4 = half a row, exactly 25
// iterations for every thread. __ldcs: data read exactly once.
// ---------------------------------------------------------------------------
__global__ void __launch_bounds__(TPB)
sumexp_kernel(const float* __restrict__ input)
{
    const int row  = blockIdx.x >> 1;
    const int half = blockIdx.x & 1;
    const float4* __restrict__ p =
        reinterpret_cast<const float4*>(input + (size_t)row * N_COLS) + half * HALF4;

    float s0 = 0.f, s1 = 0.f, s2 = 0.f, s3 = 0.f;

    #pragma unroll
    for (int it = 0; it < NITER; it++) {
        float4 v[BATCH];
        const int base = it * (TPB * BATCH) + threadIdx.x;
        #pragma unroll
        for (int k = 0; k < BATCH; k++)
            v[k] = __ldcs(p + base + k * TPB);
        #pragma unroll
        for (int k = 0; k < BATCH; k++) {
            s0 += fast_exp_term(v[k].x);
            s1 += fast_exp_term(v[k].y);
            s2 += fast_exp_term(v[k].z);
            s3 += fast_exp_term(v[k].w);
        }
    }
    float s = (s0 + s1) + (s2 + s3);

    #pragma unroll
    for (int o = 16; o > 0; o >>= 1)
        s += __shfl_xor_sync(0xffffffffu, s, o);

    __shared__ float warp_s[TPB / 32];
    if ((threadIdx.x & 31) == 0) warp_s[threadIdx.x >> 5] = s;
    __syncthreads();

    if (threadIdx.x == 0) {
        float S = 0.f;
        #pragma unroll
        for (int w = 0; w < TPB / 32; w++) S += warp_s[w];
        g_half_sum[blockIdx.x] = S;
    }
}

// ---------------------------------------------------------------------------
// Kernel 2 (32 blocks x 128 threads, 1 row/thread): dtype detection
// (redundant per block; L2 hits for blocks 1..31) + target gather + focal
// epilogue + per-block partial + FUSED last-block final reduction
// (R13-validated mechanism: fixed lane order -> deterministic; ticket
// counter reset by last block for graph replay).
//
// Dtype detection: int32 data misread as int64 decodes outside [0,32000)
// for nearly every 8-byte slot; first 2048 slots = 16 KB = int32 buf size.
// ---------------------------------------------------------------------------
__global__ void __launch_bounds__(GTPB)
gather_focal_kernel(const float* __restrict__ input, const void* __restrict__ tgt,
                    float* __restrict__ out)
{
    const int tid = threadIdx.x;
    const long long* t64 = (const long long*)tgt;

    int ok = 1;
    #pragma unroll
    for (int k = 0; k < (N_ROWS / 2) / GTPB; k++) {   // 16 slots/thread
        long long v = t64[tid + k * GTPB];
        if (v < 0 || v >= (long long)N_COLS) ok = 0;
    }
    const int is64 = __syncthreads_and(ok);

    const int row = blockIdx.x * GTPB + tid;
    long long t = is64 ? t64[row] : (long long)(((const int*)tgt)[row]);
    float S  = g_half_sum[2 * row] + g_half_sum[2 * row + 1];  // fixed order
    float xt = __ldg(input + (size_t)row * N_COLS + (size_t)t);
    float logpt = xt - logf(S);
    float pt    = expf(logpt);
    float omp   = 1.0f - pt;
    // gamma: 5 iff pt < 0.2, else 3 (GAMMA_SELF == GAMMA_LT_05 == 3)
    float w3    = omp * omp * omp;
    float wgt   = (pt < 0.2f) ? w3 * omp * omp : w3;
    float acc   = -wgt * logpt;

    #pragma unroll
    for (int o = 16; o > 0; o >>= 1)
        acc += __shfl_xor_sync(0xffffffffu, acc, o);

    __shared__ float warp_s[GTPB / 32];
    __shared__ int   is_last;
    if ((tid & 31) == 0) warp_s[tid >> 5] = acc;
    __syncthreads();

    if (tid == 0) {
        float T = 0.f;
        #pragma unroll
        for (int w = 0; w < GTPB / 32; w++) T += warp_s[w];
        g_part[blockIdx.x] = T;
        __threadfence();
        is_last = (atomicAdd(&g_arrive, 1) == GBLK - 1);
    }
    __syncthreads();

    if (is_last && tid < 32) {
        __threadfence();                 // acquire all g_part writes
        float s = g_part[tid];
        #pragma unroll
        for (int o = 16; o > 0; o >>= 1)
            s += __shfl_xor_sync(0xffffffffu, s, o);
        if (tid == 0) {
            out[0]   = s;
            g_arrive = 0;                // reset for next graph replay
        }
    }
}

extern "C" void kernel_launch(void* const* d_in, const int* in_sizes, int n_in,
                              void* d_out, int out_size) {
    const float* input = (const float*)d_in[0];
    const void*  tgt   = d_in[1];
    (void)in_sizes; (void)n_in; (void)out_size;

    sumexp_kernel<<<2 * N_ROWS, TPB>>>(input);
    gather_focal_kernel<<<GBLK, GTPB>>>(input, tgt, (float*)d_out);
}